// round 7
// baseline (speedup 1.0000x reference)
#include <cuda_runtime.h>
#include <cuda_fp16.h>
#include <cstdint>
#include <math.h>

// ---------------- problem constants ----------------
#define N_TOK 8192
#define DIM   1024
#define HID   2048
#define OUTD  1024
#define NEXP  8
#define NE9   9              // 8 routed + 1 shared
#define TOPK  2
#define EPSBN 1e-5f

// ---------------- GEMM tiling ----------------
#define BM 128
#define BN 128
#define BKC 64               // K elements per pipeline stage
#define NSTAGE 3
#define PITCH 72             // smem row pitch in halves

#define ROWS_RTD (N_TOK*TOPK + NEXP*BM)     // 17408 routed (padded)
#define ROWS_TOT (ROWS_RTD + N_TOK)         // 25600 incl. shared segment

#define A_STG_H (128*PITCH)
#define STAGE_H (2*A_STG_H)
#define PAR_OFF_B (NSTAGE*STAGE_H*2)        // 110592 bytes
#define SMEM_BYTES (PAR_OFF_B + 3*128*4)    // 112128 bytes

// ---------------- static device scratch ----------------
__device__ __half g_x16[(size_t)N_TOK * DIM];
__device__ __half g_w1[(size_t)NE9 * HID * DIM];
__device__ __half g_w2[(size_t)NE9 * HID * HID];
__device__ __half g_w3[(size_t)NE9 * OUTD * HID];
__device__ __half g_bufA[(size_t)ROWS_TOT * HID];
__device__ __half g_bufB[(size_t)ROWS_TOT * HID];
// combined epilogue params
__device__ float g_p1b[NE9 * HID], g_p1s[NE9 * HID], g_p1h[NE9 * HID];
__device__ float g_p2b[NE9 * HID], g_p2s[NE9 * HID], g_p2h[NE9 * HID];
__device__ float g_p3b[NE9 * OUTD];
// routing
__device__ int   g_cnt[NEXP];
__device__ int   g_off[NE9 + 1];
__device__ int   g_fill[NEXP];
__device__ int   g_tok2[N_TOK * TOPK];
__device__ float g_w2g[N_TOK * TOPK];
__device__ int   g_rowtok[ROWS_TOT];
__device__ float g_roww[ROWS_TOT];

// ---------------- helpers (family-agnostic sm_80+ PTX) ----------------
__device__ __forceinline__ uint32_t smem_u32(const void* p) {
    uint32_t a;
    asm("{ .reg .u64 t; cvta.to.shared.u64 t, %1; cvt.u32.u64 %0, t; }" : "=r"(a) : "l"(p));
    return a;
}
__device__ __forceinline__ void cp16(uint32_t dst, const void* src, int szbytes) {
    asm volatile("cp.async.cg.shared.global [%0], [%1], 16, %2;"
                 :: "r"(dst), "l"(src), "r"(szbytes) : "memory");
}
template<int N> __device__ __forceinline__ void cp_wait() {
    asm volatile("cp.async.wait_group %0;" :: "n"(N) : "memory");
}
__device__ __forceinline__ void cp_commit() {
    asm volatile("cp.async.commit_group;" ::: "memory");
}
__device__ __forceinline__ void ldsm_x4(uint32_t addr, uint32_t* r) {
    asm volatile("ldmatrix.sync.aligned.m8n8.x4.shared.b16 {%0,%1,%2,%3}, [%4];"
                 : "=r"(r[0]), "=r"(r[1]), "=r"(r[2]), "=r"(r[3]) : "r"(addr));
}
__device__ __forceinline__ void mma_f16(float* c, const uint32_t* a, uint32_t b0, uint32_t b1) {
    asm volatile("mma.sync.aligned.m16n8k16.row.col.f32.f16.f16.f32 "
                 "{%0,%1,%2,%3}, {%4,%5,%6,%7}, {%8,%9}, {%0,%1,%2,%3};"
                 : "+f"(c[0]), "+f"(c[1]), "+f"(c[2]), "+f"(c[3])
                 : "r"(a[0]), "r"(a[1]), "r"(a[2]), "r"(a[3]), "r"(b0), "r"(b1));
}

// ---------------- routing kernels ----------------
__global__ void k_init() {
    int i = blockIdx.x * blockDim.x + threadIdx.x;
    if (i < ROWS_TOT) g_rowtok[i] = -1;
    if (i < NEXP)     g_cnt[i] = 0;
}

__global__ void k_gate(const float* __restrict__ x, const float* __restrict__ Wg) {
    int warp = threadIdx.x >> 5;
    int lane = threadIdx.x & 31;
    int t = blockIdx.x * 8 + warp;
    if (t >= N_TOK) return;
    const float* xr = x + (size_t)t * DIM;
    float acc[NEXP];
#pragma unroll
    for (int e = 0; e < NEXP; e++) acc[e] = 0.f;
    for (int d = lane; d < DIM; d += 32) {
        float xv = xr[d];
#pragma unroll
        for (int e = 0; e < NEXP; e++) acc[e] = fmaf(xv, Wg[e * DIM + d], acc[e]);
    }
#pragma unroll
    for (int e = 0; e < NEXP; e++)
#pragma unroll
        for (int s = 16; s > 0; s >>= 1) acc[e] += __shfl_xor_sync(0xffffffffu, acc[e], s);
    if (lane == 0) {
        float mx = acc[0];
#pragma unroll
        for (int e = 1; e < NEXP; e++) mx = fmaxf(mx, acc[e]);
        float p[NEXP], sum = 0.f;
#pragma unroll
        for (int e = 0; e < NEXP; e++) { p[e] = expf(acc[e] - mx); sum += p[e]; }
        float inv = 1.f / sum;
#pragma unroll
        for (int e = 0; e < NEXP; e++) p[e] *= inv;
        int i0 = 0;
#pragma unroll
        for (int e = 1; e < NEXP; e++) if (p[e] > p[i0]) i0 = e;
        int i1 = (i0 == 0) ? 1 : 0;
#pragma unroll
        for (int e = 0; e < NEXP; e++) if (e != i0 && p[e] > p[i1]) i1 = e;
        float den = p[i0] + p[i1] + 1e-20f;
        g_tok2[2 * t + 0] = i0; g_w2g[2 * t + 0] = p[i0] / den;
        g_tok2[2 * t + 1] = i1; g_w2g[2 * t + 1] = p[i1] / den;
        atomicAdd(&g_cnt[i0], 1);
        atomicAdd(&g_cnt[i1], 1);
    }
}

__global__ void k_offsets() {
    if (threadIdx.x == 0) {
        int o = 0;
        for (int e = 0; e < NEXP; e++) { g_off[e] = o; o += ((g_cnt[e] + BM - 1) / BM) * BM; }
        g_off[NEXP] = o;                 // start of shared segment
        g_off[NE9]  = o + N_TOK;         // total rows
    }
    if (threadIdx.x < NEXP) g_fill[threadIdx.x] = 0;
}

__global__ void k_scatter() {
    int t = blockIdx.x * blockDim.x + threadIdx.x;
    if (t >= N_TOK) return;
#pragma unroll
    for (int s = 0; s < TOPK; s++) {
        int e = g_tok2[2 * t + s];
        int pos = g_off[e] + atomicAdd(&g_fill[e], 1);
        g_rowtok[pos] = t;
        g_roww[pos]  = g_w2g[2 * t + s];
    }
    // shared-expert segment: every token, weight 1
    int sp = g_off[NEXP] + t;
    g_rowtok[sp] = t;
    g_roww[sp]  = 1.0f;
}

// ---------------- combined epilogue params (once per call) ----------------
__global__ void k_params(const float* b1, const float* g1, const float* be1,
                         const float* m1, const float* v1,
                         const float* b2, const float* g2, const float* be2,
                         const float* m2, const float* v2,
                         const float* b3,
                         const float* sb1, const float* sg1, const float* sbe1,
                         const float* sm1, const float* sv1,
                         const float* sb2, const float* sg2, const float* sbe2,
                         const float* sm2, const float* sv2,
                         const float* sb3)
{
    int idx = blockIdx.x * blockDim.x + threadIdx.x;
    if (idx >= NE9 * HID) return;
    int e = idx / HID, n = idx % HID;
    bool sh = (e == NEXP);
    size_t pe = (size_t)e * HID + n;
    // layer 1
    {
        float bb = sh ? sb1[n] : b1[pe];
        float gg = sh ? sg1[n] : g1[pe];
        float be = sh ? sbe1[n] : be1[pe];
        float mm = sh ? sm1[n] : m1[pe];
        float vv = sh ? sv1[n] : v1[pe];
        float s = gg * rsqrtf(vv + EPSBN);
        g_p1b[idx] = bb; g_p1s[idx] = s; g_p1h[idx] = fmaf(-mm, s, be);
    }
    // layer 2
    {
        float bb = sh ? sb2[n] : b2[pe];
        float gg = sh ? sg2[n] : g2[pe];
        float be = sh ? sbe2[n] : be2[pe];
        float mm = sh ? sm2[n] : m2[pe];
        float vv = sh ? sv2[n] : v2[pe];
        float s = gg * rsqrtf(vv + EPSBN);
        g_p2b[idx] = bb; g_p2s[idx] = s; g_p2h[idx] = fmaf(-mm, s, be);
    }
    // layer 3 (bias only)
    if (n < OUTD) {
        int i3 = e * OUTD + n;
        g_p3b[i3] = sh ? sb3[n] : b3[(size_t)e * OUTD + n];
    }
}

// ---------------- fp32 -> fp16 conversion ----------------
__global__ void k_cvt(const float* __restrict__ s, __half* __restrict__ d, int n) {
    int i = (blockIdx.x * blockDim.x + threadIdx.x) * 4;
    if (i >= n) return;
    float4 v = *(const float4*)(s + i);
    *(__half2*)(d + i)     = __floats2half2_rn(v.x, v.y);
    *(__half2*)(d + i + 2) = __floats2half2_rn(v.z, v.w);
}

__global__ void k_zero(float* __restrict__ p, int n4) {
    int i = blockIdx.x * blockDim.x + threadIdx.x;
    if (i < n4) ((float4*)p)[i] = make_float4(0.f, 0.f, 0.f, 0.f);
}

// ---------------- fp16 mma.sync fused GEMM ----------------
// CTA tile 128x128, 4 warps (2x2), warp tile 64x64, m16n8k16 f16->f32.
// 3-stage cp.async pipeline, K-chunk 64, ldmatrix fragment loads.
// Expert id from g_off scan (9 segments; e==8 is the shared expert).
// EPI 0: relu+BN -> __half store   EPI 2: w*sigmoid atomicAdd scatter -> f32
template<int EPI, bool GATHER>
__global__ void __launch_bounds__(128, 2)
gemm_h(const __half* __restrict__ X,
       const __half* __restrict__ Wb,
       const float* __restrict__ pb,
       const float* __restrict__ ps, const float* __restrict__ ph,
       void* __restrict__ outv,
       int Kd, int Hout, long wstride)
{
    extern __shared__ char smc[];
    __half* sm = (__half*)smc;
    int tid = threadIdx.x;
    int wid = tid >> 5;
    int lid = tid & 31;

    const int* off = g_off;
    int tileStart = blockIdx.y * BM;
    if (tileStart >= off[NE9]) return;
    int e = 0;
    while (e < NEXP && off[e + 1] <= tileStart) e++;
    const __half* W = Wb + (size_t)e * (size_t)wstride;
    int nbase = blockIdx.x * BN;

    // epilogue params to smem
    float* par_b  = (float*)(smc + PAR_OFF_B);
    float* par_sc = par_b + 128;
    float* par_sh = par_b + 256;
    {
        int n = e * Hout + nbase;
#pragma unroll
        for (int i = tid; i < 128; i += 128) {
            par_b[i] = pb[n + i];
            if (EPI == 0) { par_sc[i] = ps[n + i]; par_sh[i] = ph[n + i]; }
        }
    }

    // producer mapping: 128 threads; 8 row-groups of 16 rows; 8 threads/row
    int lrow = tid >> 3;            // 0..15
    int lc   = (tid & 7) * 8;       // half offset
    int arow[8]; unsigned amask = 0;
#pragma unroll
    for (int i = 0; i < 8; i++) {
        int r = lrow + 16 * i;
        if (GATHER) {
            int tok = g_rowtok[tileStart + r];
            arow[i] = (tok >= 0) ? tok : 0;
            if (tok >= 0) amask |= (1u << i);
        } else {
            arow[i] = tileStart + r;
            amask |= (1u << i);
        }
    }
    const __half* bbase = W + (size_t)(nbase + lrow) * Kd + lc;

    uint32_t sb = smem_u32(sm);
    uint32_t adst = sb + (uint32_t)(lrow * PITCH + lc) * 2u;
    uint32_t bdst = adst + (uint32_t)A_STG_H * 2u;

    float acc[32][4];
#pragma unroll
    for (int i = 0; i < 32; i++)
#pragma unroll
        for (int j = 0; j < 4; j++) acc[i][j] = 0.f;

    int warpM = wid & 1;           // 0..1 -> 64 rows
    int warpN = wid >> 1;          // 0..1 -> 64 cols
    int g = lid >> 2, t = lid & 3;

    int aRowSel = lid & 15;
    int aColSel = (lid >> 4) * 8;
    int bNoff   = (lid & 7) + ((lid >> 4) << 3);
    int bKoff   = ((lid >> 3) & 1) * 8;

    int Nc = Kd / BKC;

    // prologue: stages 0,1
#pragma unroll
    for (int p = 0; p < 2; p++) {
        uint32_t so = (uint32_t)(p * STAGE_H) * 2u;
        int k0 = p * BKC;
#pragma unroll
        for (int i = 0; i < 8; i++) {
            cp16(adst + so + (uint32_t)(16 * i * PITCH) * 2u,
                 X + (size_t)arow[i] * Kd + k0 + lc, (amask >> i & 1) ? 16 : 0);
            cp16(bdst + so + (uint32_t)(16 * i * PITCH) * 2u,
                 bbase + (size_t)(16 * i) * Kd + k0, 16);
        }
        cp_commit();
    }

    int stage = 0;
    for (int c = 0; c < Nc; c++) {
        if (c + 1 < Nc) cp_wait<1>(); else cp_wait<0>();
        __syncthreads();

        if (c + 2 < Nc) {
            int sidx = (c + 2) % NSTAGE;
            uint32_t so = (uint32_t)(sidx * STAGE_H) * 2u;
            int k0 = (c + 2) * BKC;
#pragma unroll
            for (int i = 0; i < 8; i++) {
                cp16(adst + so + (uint32_t)(16 * i * PITCH) * 2u,
                     X + (size_t)arow[i] * Kd + k0 + lc, (amask >> i & 1) ? 16 : 0);
                cp16(bdst + so + (uint32_t)(16 * i * PITCH) * 2u,
                     bbase + (size_t)(16 * i) * Kd + k0, 16);
            }
            cp_commit();
        }

        uint32_t As = sb + (uint32_t)(stage * STAGE_H) * 2u;
        uint32_t Bs = As + (uint32_t)A_STG_H * 2u;
#pragma unroll
        for (int ks = 0; ks < 4; ks++) {
            uint32_t a[4][4];
#pragma unroll
            for (int mt = 0; mt < 4; mt++) {
                uint32_t addr = As + (uint32_t)((warpM * 64 + mt * 16 + aRowSel) * PITCH
                                                + ks * 16 + aColSel) * 2u;
                ldsm_x4(addr, a[mt]);
            }
            uint32_t b[4][4];
#pragma unroll
            for (int ntp = 0; ntp < 4; ntp++) {
                uint32_t addr = Bs + (uint32_t)((warpN * 64 + ntp * 16 + bNoff) * PITCH
                                                + ks * 16 + bKoff) * 2u;
                ldsm_x4(addr, b[ntp]);
            }
#pragma unroll
            for (int mt = 0; mt < 4; mt++) {
#pragma unroll
                for (int nt = 0; nt < 8; nt++) {
                    uint32_t b0 = b[nt >> 1][(nt & 1) * 2];
                    uint32_t b1 = b[nt >> 1][(nt & 1) * 2 + 1];
                    mma_f16(acc[mt * 8 + nt], a[mt], b0, b1);
                }
            }
        }
        stage = (stage + 1 == NSTAGE) ? 0 : stage + 1;
    }

    // ---- epilogue ----
    __half* out16 = (__half*)outv;
    float*  outf  = (float*)outv;
#pragma unroll
    for (int mt = 0; mt < 4; mt++) {
        int rl0 = warpM * 64 + mt * 16 + g;
        int r0 = tileStart + rl0;
        int r1 = r0 + 8;
        int tok0 = 0, tok1 = 0; float w0 = 0.f, w1 = 0.f;
        if (EPI == 2) {
            tok0 = g_rowtok[r0]; tok1 = g_rowtok[r1];
            w0 = g_roww[r0];     w1 = g_roww[r1];
        }
#pragma unroll
        for (int nt = 0; nt < 8; nt++) {
            float* c = acc[mt * 8 + nt];
            int colL = warpN * 64 + nt * 8 + 2 * t;
            int col = nbase + colL;
            if (EPI == 0) {
                float b0 = par_b[colL], b1 = par_b[colL + 1];
                float s0 = par_sc[colL], s1 = par_sc[colL + 1];
                float h0 = par_sh[colL], h1 = par_sh[colL + 1];
                __half2 o0 = __floats2half2_rn(
                    fmaf(fmaxf(c[0] + b0, 0.f), s0, h0),
                    fmaf(fmaxf(c[1] + b1, 0.f), s1, h1));
                __half2 o1 = __floats2half2_rn(
                    fmaf(fmaxf(c[2] + b0, 0.f), s0, h0),
                    fmaf(fmaxf(c[3] + b1, 0.f), s1, h1));
                *(__half2*)(out16 + (size_t)r0 * Hout + col) = o0;
                *(__half2*)(out16 + (size_t)r1 * Hout + col) = o1;
            } else {
                float b0 = par_b[colL], b1 = par_b[colL + 1];
                if (tok0 >= 0) {
                    float* orow = outf + (size_t)tok0 * Hout + col;
                    atomicAdd(&orow[0], w0 * (1.f / (1.f + __expf(-(c[0] + b0)))));
                    atomicAdd(&orow[1], w0 * (1.f / (1.f + __expf(-(c[1] + b1)))));
                }
                if (tok1 >= 0) {
                    float* orow = outf + (size_t)tok1 * Hout + col;
                    atomicAdd(&orow[0], w1 * (1.f / (1.f + __expf(-(c[2] + b0)))));
                    atomicAdd(&orow[1], w1 * (1.f / (1.f + __expf(-(c[3] + b1)))));
                }
            }
        }
    }
}

// ---------------- launch ----------------
extern "C" void kernel_launch(void* const* d_in, const int* in_sizes, int n_in,
                              void* d_out, int out_size) {
    (void)in_sizes; (void)n_in; (void)out_size;

    const float* x   = (const float*)d_in[0];
    const float* Wg  = (const float*)d_in[1];
    const float* W1  = (const float*)d_in[2];
    const float* b1  = (const float*)d_in[3];
    const float* g1  = (const float*)d_in[4];
    const float* be1 = (const float*)d_in[5];
    const float* m1  = (const float*)d_in[6];
    const float* v1  = (const float*)d_in[7];
    const float* W2  = (const float*)d_in[8];
    const float* b2  = (const float*)d_in[9];
    const float* g2  = (const float*)d_in[10];
    const float* be2 = (const float*)d_in[11];
    const float* m2  = (const float*)d_in[12];
    const float* v2  = (const float*)d_in[13];
    const float* W3  = (const float*)d_in[14];
    const float* b3  = (const float*)d_in[15];
    const float* sW1 = (const float*)d_in[16];
    const float* sb1 = (const float*)d_in[17];
    const float* sg1 = (const float*)d_in[18];
    const float* sbe1= (const float*)d_in[19];
    const float* sm1 = (const float*)d_in[20];
    const float* sv1 = (const float*)d_in[21];
    const float* sW2 = (const float*)d_in[22];
    const float* sb2 = (const float*)d_in[23];
    const float* sg2 = (const float*)d_in[24];
    const float* sbe2= (const float*)d_in[25];
    const float* sm2 = (const float*)d_in[26];
    const float* sv2 = (const float*)d_in[27];
    const float* sW3 = (const float*)d_in[28];
    const float* sb3 = (const float*)d_in[29];
    float* out = (float*)d_out;

    __half *x16, *w1h, *w2h, *w3h, *bufA, *bufB;
    float *p1b, *p1s, *p1h, *p2b, *p2s, *p2h, *p3b;
    cudaGetSymbolAddress((void**)&x16,  g_x16);
    cudaGetSymbolAddress((void**)&w1h,  g_w1);
    cudaGetSymbolAddress((void**)&w2h,  g_w2);
    cudaGetSymbolAddress((void**)&w3h,  g_w3);
    cudaGetSymbolAddress((void**)&bufA, g_bufA);
    cudaGetSymbolAddress((void**)&bufB, g_bufB);
    cudaGetSymbolAddress((void**)&p1b,  g_p1b);
    cudaGetSymbolAddress((void**)&p1s,  g_p1s);
    cudaGetSymbolAddress((void**)&p1h,  g_p1h);
    cudaGetSymbolAddress((void**)&p2b,  g_p2b);
    cudaGetSymbolAddress((void**)&p2s,  g_p2s);
    cudaGetSymbolAddress((void**)&p2h,  g_p2h);
    cudaGetSymbolAddress((void**)&p3b,  g_p3b);

    cudaFuncSetAttribute(gemm_h<0, true>,  cudaFuncAttributeMaxDynamicSharedMemorySize, SMEM_BYTES);
    cudaFuncSetAttribute(gemm_h<0, false>, cudaFuncAttributeMaxDynamicSharedMemorySize, SMEM_BYTES);
    cudaFuncSetAttribute(gemm_h<2, false>, cudaFuncAttributeMaxDynamicSharedMemorySize, SMEM_BYTES);

    // routing + params + zero + conversions
    k_init<<<(ROWS_TOT + 255) / 256, 256>>>();
    k_gate<<<N_TOK / 8, 256>>>(x, Wg);
    k_offsets<<<1, 32>>>();
    k_scatter<<<(N_TOK + 255) / 256, 256>>>();
    k_params<<<(NE9 * HID + 255) / 256, 256>>>(
        b1, g1, be1, m1, v1, b2, g2, be2, m2, v2, b3,
        sb1, sg1, sbe1, sm1, sv1, sb2, sg2, sbe2, sm2, sv2, sb3);
    k_zero<<<(N_TOK * OUTD / 4 + 255) / 256, 256>>>(out, N_TOK * OUTD / 4);

    {
        struct { const float* s; __half* d; size_t n; } cv[7] = {
            { x,   x16, (size_t)N_TOK * DIM },
            { W1,  w1h, (size_t)NEXP * HID * DIM },
            { sW1, w1h + (size_t)NEXP * HID * DIM, (size_t)HID * DIM },
            { W2,  w2h, (size_t)NEXP * HID * HID },
            { sW2, w2h + (size_t)NEXP * HID * HID, (size_t)HID * HID },
            { W3,  w3h, (size_t)NEXP * OUTD * HID },
            { sW3, w3h + (size_t)NEXP * OUTD * HID, (size_t)OUTD * HID },
        };
        for (int i = 0; i < 7; i++)
            k_cvt<<<(int)((cv[i].n / 4 + 255) / 256), 256>>>(cv[i].s, cv[i].d, (int)cv[i].n);
    }

    // unified 9-expert chain: gather(x16) -> bufA -> bufB -> out (atomic)
    dim3 grid1(HID / BN,  ROWS_TOT / BM);
    dim3 grid2(HID / BN,  ROWS_TOT / BM);
    dim3 grid3(OUTD / BN, ROWS_TOT / BM);
    gemm_h<0, true><<<grid1, 128, SMEM_BYTES>>>(
        x16, w1h, p1b, p1s, p1h, bufA, DIM, HID, (long)HID * DIM);
    gemm_h<0, false><<<grid2, 128, SMEM_BYTES>>>(
        bufA, w2h, p2b, p2s, p2h, bufB, HID, HID, (long)HID * HID);
    gemm_h<2, false><<<grid3, 128, SMEM_BYTES>>>(
        bufB, w3h, p3b, nullptr, nullptr, out, HID, OUTD, (long)OUTD * HID);
}

// round 8
// speedup vs baseline: 1.0510x; 1.0510x over previous
#include <cuda_runtime.h>
#include <cuda_fp16.h>
#include <cstdint>
#include <math.h>

// ---------------- problem constants ----------------
#define N_TOK 8192
#define DIM   1024
#define HID   2048
#define OUTD  1024
#define NEXP  8
#define NE9   9              // 8 routed + 1 shared
#define TOPK  2
#define EPSBN 1e-5f

// ---------------- GEMM tiling (R6-proven config) ----------------
#define BM 128
#define BN 128
#define BKC 64
#define NSTAGE 3
#define PITCH 72             // smem row pitch in halves (144B = 9x16B, ldmatrix conflict-free)

#define ROWS_RTD (N_TOK*TOPK + NEXP*BM)     // 17408 routed (padded)
#define ROWS_TOT (ROWS_RTD + N_TOK)         // 25600 incl. shared segment

#define A_STG_H (128*PITCH)
#define STAGE_H (2*A_STG_H)
#define PAR_OFF_B (NSTAGE*STAGE_H*2)        // 110592 bytes
#define SMEM_BYTES (PAR_OFF_B + 3*128*4)    // 112128 bytes

// ---------------- static device scratch ----------------
__device__ __half g_x16[(size_t)N_TOK * DIM];
__device__ __half g_w1[(size_t)NE9 * HID * DIM];
__device__ __half g_w2[(size_t)NE9 * HID * HID];
__device__ __half g_w3[(size_t)NE9 * OUTD * HID];
// bufA: L1 activations (half). After L2 finishes, bufA is dead; its storage is
// reused as the L3 fp32 output scratch (ROWS_TOT*HID halves == ROWS_TOT*OUTD floats).
__device__ __half g_bufA[(size_t)ROWS_TOT * HID];
__device__ __half g_bufB[(size_t)ROWS_TOT * HID];
// combined epilogue params
__device__ float g_p1b[NE9 * HID], g_p1s[NE9 * HID], g_p1h[NE9 * HID];
__device__ float g_p2b[NE9 * HID], g_p2s[NE9 * HID], g_p2h[NE9 * HID];
__device__ float g_p3b[NE9 * OUTD];
// routing
__device__ int   g_cnt[NEXP];
__device__ int   g_off[NE9 + 1];
__device__ int   g_fill[NEXP];
__device__ int   g_tok2[N_TOK * TOPK];
__device__ float g_w2g[N_TOK * TOPK];
__device__ int   g_pos[N_TOK * TOPK];
__device__ int   g_rowtok[ROWS_TOT];

// ---------------- helpers (family-agnostic sm_80+ PTX) ----------------
__device__ __forceinline__ uint32_t smem_u32(const void* p) {
    uint32_t a;
    asm("{ .reg .u64 t; cvta.to.shared.u64 t, %1; cvt.u32.u64 %0, t; }" : "=r"(a) : "l"(p));
    return a;
}
__device__ __forceinline__ void cp16(uint32_t dst, const void* src, int szbytes) {
    asm volatile("cp.async.cg.shared.global [%0], [%1], 16, %2;"
                 :: "r"(dst), "l"(src), "r"(szbytes) : "memory");
}
template<int N> __device__ __forceinline__ void cp_wait() {
    asm volatile("cp.async.wait_group %0;" :: "n"(N) : "memory");
}
__device__ __forceinline__ void cp_commit() {
    asm volatile("cp.async.commit_group;" ::: "memory");
}
__device__ __forceinline__ void ldsm_x4(uint32_t addr, uint32_t* r) {
    asm volatile("ldmatrix.sync.aligned.m8n8.x4.shared.b16 {%0,%1,%2,%3}, [%4];"
                 : "=r"(r[0]), "=r"(r[1]), "=r"(r[2]), "=r"(r[3]) : "r"(addr));
}
__device__ __forceinline__ void mma_f16(float* c, const uint32_t* a, uint32_t b0, uint32_t b1) {
    asm volatile("mma.sync.aligned.m16n8k16.row.col.f32.f16.f16.f32 "
                 "{%0,%1,%2,%3}, {%4,%5,%6,%7}, {%8,%9}, {%0,%1,%2,%3};"
                 : "+f"(c[0]), "+f"(c[1]), "+f"(c[2]), "+f"(c[3])
                 : "r"(a[0]), "r"(a[1]), "r"(a[2]), "r"(a[3]), "r"(b0), "r"(b1));
}

// ---------------- routing kernels ----------------
__global__ void k_init() {
    int i = blockIdx.x * blockDim.x + threadIdx.x;
    if (i < ROWS_TOT) g_rowtok[i] = -1;
    if (i < NEXP)     g_cnt[i] = 0;
}

__global__ void k_gate(const float* __restrict__ x, const float* __restrict__ Wg) {
    int warp = threadIdx.x >> 5;
    int lane = threadIdx.x & 31;
    int t = blockIdx.x * 8 + warp;
    if (t >= N_TOK) return;
    const float* xr = x + (size_t)t * DIM;
    float acc[NEXP];
#pragma unroll
    for (int e = 0; e < NEXP; e++) acc[e] = 0.f;
    for (int d = lane; d < DIM; d += 32) {
        float xv = xr[d];
#pragma unroll
        for (int e = 0; e < NEXP; e++) acc[e] = fmaf(xv, Wg[e * DIM + d], acc[e]);
    }
#pragma unroll
    for (int e = 0; e < NEXP; e++)
#pragma unroll
        for (int s = 16; s > 0; s >>= 1) acc[e] += __shfl_xor_sync(0xffffffffu, acc[e], s);
    if (lane == 0) {
        float mx = acc[0];
#pragma unroll
        for (int e = 1; e < NEXP; e++) mx = fmaxf(mx, acc[e]);
        float p[NEXP], sum = 0.f;
#pragma unroll
        for (int e = 0; e < NEXP; e++) { p[e] = expf(acc[e] - mx); sum += p[e]; }
        float inv = 1.f / sum;
#pragma unroll
        for (int e = 0; e < NEXP; e++) p[e] *= inv;
        int i0 = 0;
#pragma unroll
        for (int e = 1; e < NEXP; e++) if (p[e] > p[i0]) i0 = e;
        int i1 = (i0 == 0) ? 1 : 0;
#pragma unroll
        for (int e = 0; e < NEXP; e++) if (e != i0 && p[e] > p[i1]) i1 = e;
        float den = p[i0] + p[i1] + 1e-20f;
        g_tok2[2 * t + 0] = i0; g_w2g[2 * t + 0] = p[i0] / den;
        g_tok2[2 * t + 1] = i1; g_w2g[2 * t + 1] = p[i1] / den;
        atomicAdd(&g_cnt[i0], 1);
        atomicAdd(&g_cnt[i1], 1);
    }
}

__global__ void k_offsets() {
    if (threadIdx.x == 0) {
        int o = 0;
        for (int e = 0; e < NEXP; e++) { g_off[e] = o; o += ((g_cnt[e] + BM - 1) / BM) * BM; }
        g_off[NEXP] = o;                 // start of shared segment
        g_off[NE9]  = o + N_TOK;         // total rows
    }
    if (threadIdx.x < NEXP) g_fill[threadIdx.x] = 0;
}

__global__ void k_scatter() {
    int t = blockIdx.x * blockDim.x + threadIdx.x;
    if (t >= N_TOK) return;
#pragma unroll
    for (int s = 0; s < TOPK; s++) {
        int e = g_tok2[2 * t + s];
        int pos = g_off[e] + atomicAdd(&g_fill[e], 1);
        g_rowtok[pos]    = t;
        g_pos[2 * t + s] = pos;
    }
    int sp = g_off[NEXP] + t;
    g_rowtok[sp] = t;
}

// ---------------- combined epilogue params (once per call) ----------------
__global__ void k_params(const float* b1, const float* g1, const float* be1,
                         const float* m1, const float* v1,
                         const float* b2, const float* g2, const float* be2,
                         const float* m2, const float* v2,
                         const float* b3,
                         const float* sb1, const float* sg1, const float* sbe1,
                         const float* sm1, const float* sv1,
                         const float* sb2, const float* sg2, const float* sbe2,
                         const float* sm2, const float* sv2,
                         const float* sb3)
{
    int idx = blockIdx.x * blockDim.x + threadIdx.x;
    if (idx >= NE9 * HID) return;
    int e = idx / HID, n = idx % HID;
    bool sh = (e == NEXP);
    size_t pe = (size_t)e * HID + n;
    {
        float bb = sh ? sb1[n] : b1[pe];
        float s = (sh ? sg1[n] : g1[pe]) * rsqrtf((sh ? sv1[n] : v1[pe]) + EPSBN);
        g_p1b[idx] = bb; g_p1s[idx] = s;
        g_p1h[idx] = fmaf(-(sh ? sm1[n] : m1[pe]), s, sh ? sbe1[n] : be1[pe]);
    }
    {
        float bb = sh ? sb2[n] : b2[pe];
        float s = (sh ? sg2[n] : g2[pe]) * rsqrtf((sh ? sv2[n] : v2[pe]) + EPSBN);
        g_p2b[idx] = bb; g_p2s[idx] = s;
        g_p2h[idx] = fmaf(-(sh ? sm2[n] : m2[pe]), s, sh ? sbe2[n] : be2[pe]);
    }
    if (n < OUTD) {
        g_p3b[e * OUTD + n] = sh ? sb3[n] : b3[(size_t)e * OUTD + n];
    }
}

// ---------------- fp32 -> fp16 conversion ----------------
__global__ void k_cvt(const float* __restrict__ s, __half* __restrict__ d, int n) {
    int i = (blockIdx.x * blockDim.x + threadIdx.x) * 4;
    if (i >= n) return;
    float4 v = *(const float4*)(s + i);
    *(__half2*)(d + i)     = __floats2half2_rn(v.x, v.y);
    *(__half2*)(d + i + 2) = __floats2half2_rn(v.z, v.w);
}

// ---------------- final combine: out[t] = w0*C[p0] + w1*C[p1] + C[shared+t] ---
__global__ void k_combine(const float* __restrict__ C, float* __restrict__ out) {
    int idx = blockIdx.x * blockDim.x + threadIdx.x;   // one float4 per thread
    if (idx >= N_TOK * (OUTD / 4)) return;
    int t  = idx / (OUTD / 4);
    int c4 = (idx % (OUTD / 4)) * 4;
    int p0 = g_pos[2 * t], p1 = g_pos[2 * t + 1];
    float w0 = g_w2g[2 * t], w1 = g_w2g[2 * t + 1];
    int sp = g_off[NEXP] + t;
    float4 a = *(const float4*)(C + (size_t)p0 * OUTD + c4);
    float4 b = *(const float4*)(C + (size_t)p1 * OUTD + c4);
    float4 s = *(const float4*)(C + (size_t)sp * OUTD + c4);
    float4 o;
    o.x = fmaf(w0, a.x, fmaf(w1, b.x, s.x));
    o.y = fmaf(w0, a.y, fmaf(w1, b.y, s.y));
    o.z = fmaf(w0, a.z, fmaf(w1, b.z, s.z));
    o.w = fmaf(w0, a.w, fmaf(w1, b.w, s.w));
    *(float4*)(out + (size_t)t * OUTD + c4) = o;
}

// ---------------- fp16 mma.sync fused GEMM (R6 engine, unified experts) -------
// CTA tile 128x128, 8 warps (2x4), warp tile 64x32, m16n8k16 f16->f32.
// 3-stage cp.async pipeline, K-chunk 64, ldmatrix fragment loads, 2 CTAs/SM.
// EPI 0: relu+BN -> __half store    EPI 1: sigmoid -> f32 row-indexed store
template<int EPI, bool GATHER>
__global__ void __launch_bounds__(256, 2)
gemm_h(const __half* __restrict__ X,
       const __half* __restrict__ Wb,
       const float* __restrict__ pb,
       const float* __restrict__ ps, const float* __restrict__ ph,
       void* __restrict__ outv,
       int Kd, int Hout, long wstride)
{
    extern __shared__ char smc[];
    __half* sm = (__half*)smc;
    int tid = threadIdx.x;
    int wid = tid >> 5;
    int lid = tid & 31;

    const int* off = g_off;
    int tileStart = blockIdx.y * BM;
    if (tileStart >= off[NE9]) return;
    int e = 0;
    while (e < NEXP && off[e + 1] <= tileStart) e++;
    const __half* W = Wb + (size_t)e * (size_t)wstride;
    int nbase = blockIdx.x * BN;

    float* par_b  = (float*)(smc + PAR_OFF_B);
    float* par_sc = par_b + 128;
    float* par_sh = par_b + 256;
    if (tid < 128) {
        int n = e * Hout + nbase + tid;
        par_b[tid] = pb[n];
        if (EPI == 0) { par_sc[tid] = ps[n]; par_sh[tid] = ph[n]; }
    }

    int lrow = tid >> 3;
    int lc   = (tid & 7) * 8;
    int arow[4]; unsigned amask = 0;
#pragma unroll
    for (int i = 0; i < 4; i++) {
        int r = lrow + 32 * i;
        if (GATHER) {
            int tok = g_rowtok[tileStart + r];
            arow[i] = (tok >= 0) ? tok : 0;
            if (tok >= 0) amask |= (1u << i);
        } else {
            arow[i] = tileStart + r;
            amask |= (1u << i);
        }
    }
    const __half* bbase = W + (size_t)(nbase + lrow) * Kd + lc;

    uint32_t sb = smem_u32(sm);
    uint32_t adst = sb + (uint32_t)(lrow * PITCH + lc) * 2u;
    uint32_t bdst = adst + (uint32_t)A_STG_H * 2u;

    float acc[16][4];
#pragma unroll
    for (int i = 0; i < 16; i++)
#pragma unroll
        for (int j = 0; j < 4; j++) acc[i][j] = 0.f;

    int warpM = wid & 1;
    int warpN = wid >> 1;
    int g = lid >> 2, t = lid & 3;

    int aRowSel = lid & 15;
    int aColSel = (lid >> 4) * 8;
    int bNoff   = (lid & 7) + ((lid >> 4) << 3);
    int bKoff   = ((lid >> 3) & 1) * 8;

    int Nc = Kd / BKC;

#pragma unroll
    for (int p = 0; p < 2; p++) {
        uint32_t so = (uint32_t)(p * STAGE_H) * 2u;
        int k0 = p * BKC;
#pragma unroll
        for (int i = 0; i < 4; i++) {
            cp16(adst + so + (uint32_t)(32 * i * PITCH) * 2u,
                 X + (size_t)arow[i] * Kd + k0 + lc, (amask >> i & 1) ? 16 : 0);
            cp16(bdst + so + (uint32_t)(32 * i * PITCH) * 2u,
                 bbase + (size_t)(32 * i) * Kd + k0, 16);
        }
        cp_commit();
    }

    int stage = 0;
    for (int c = 0; c < Nc; c++) {
        if (c + 1 < Nc) cp_wait<1>(); else cp_wait<0>();
        __syncthreads();

        if (c + 2 < Nc) {
            int sidx = (c + 2) % NSTAGE;
            uint32_t so = (uint32_t)(sidx * STAGE_H) * 2u;
            int k0 = (c + 2) * BKC;
#pragma unroll
            for (int i = 0; i < 4; i++) {
                cp16(adst + so + (uint32_t)(32 * i * PITCH) * 2u,
                     X + (size_t)arow[i] * Kd + k0 + lc, (amask >> i & 1) ? 16 : 0);
                cp16(bdst + so + (uint32_t)(32 * i * PITCH) * 2u,
                     bbase + (size_t)(32 * i) * Kd + k0, 16);
            }
            cp_commit();
        }

        uint32_t As = sb + (uint32_t)(stage * STAGE_H) * 2u;
        uint32_t Bs = As + (uint32_t)A_STG_H * 2u;
#pragma unroll
        for (int ks = 0; ks < 4; ks++) {
            uint32_t a[4][4];
#pragma unroll
            for (int mt = 0; mt < 4; mt++) {
                uint32_t addr = As + (uint32_t)((warpM * 64 + mt * 16 + aRowSel) * PITCH
                                                + ks * 16 + aColSel) * 2u;
                ldsm_x4(addr, a[mt]);
            }
            uint32_t b[2][4];
#pragma unroll
            for (int ntp = 0; ntp < 2; ntp++) {
                uint32_t addr = Bs + (uint32_t)((warpN * 32 + ntp * 16 + bNoff) * PITCH
                                                + ks * 16 + bKoff) * 2u;
                ldsm_x4(addr, b[ntp]);
            }
#pragma unroll
            for (int mt = 0; mt < 4; mt++) {
#pragma unroll
                for (int nt = 0; nt < 4; nt++) {
                    uint32_t b0 = b[nt >> 1][(nt & 1) * 2];
                    uint32_t b1 = b[nt >> 1][(nt & 1) * 2 + 1];
                    mma_f16(acc[mt * 4 + nt], a[mt], b0, b1);
                }
            }
        }
        stage = (stage + 1 == NSTAGE) ? 0 : stage + 1;
    }

    __half* out16 = (__half*)outv;
    float*  outf  = (float*)outv;
#pragma unroll
    for (int mt = 0; mt < 4; mt++) {
        int rl0 = warpM * 64 + mt * 16 + g;
        int r0 = tileStart + rl0;
        int r1 = r0 + 8;
#pragma unroll
        for (int nt = 0; nt < 4; nt++) {
            float* c = acc[mt * 4 + nt];
            int colL = warpN * 32 + nt * 8 + 2 * t;
            int col = nbase + colL;
            if (EPI == 0) {
                float b0 = par_b[colL], b1 = par_b[colL + 1];
                float s0 = par_sc[colL], s1 = par_sc[colL + 1];
                float h0 = par_sh[colL], h1 = par_sh[colL + 1];
                __half2 o0 = __floats2half2_rn(
                    fmaf(fmaxf(c[0] + b0, 0.f), s0, h0),
                    fmaf(fmaxf(c[1] + b1, 0.f), s1, h1));
                __half2 o1 = __floats2half2_rn(
                    fmaf(fmaxf(c[2] + b0, 0.f), s0, h0),
                    fmaf(fmaxf(c[3] + b1, 0.f), s1, h1));
                *(__half2*)(out16 + (size_t)r0 * Hout + col) = o0;
                *(__half2*)(out16 + (size_t)r1 * Hout + col) = o1;
            } else {
                float b0 = par_b[colL], b1 = par_b[colL + 1];
                float2 o0, o1;
                o0.x = 1.f / (1.f + __expf(-(c[0] + b0)));
                o0.y = 1.f / (1.f + __expf(-(c[1] + b1)));
                o1.x = 1.f / (1.f + __expf(-(c[2] + b0)));
                o1.y = 1.f / (1.f + __expf(-(c[3] + b1)));
                *(float2*)(outf + (size_t)r0 * Hout + col) = o0;
                *(float2*)(outf + (size_t)r1 * Hout + col) = o1;
            }
        }
    }
}

// ---------------- launch ----------------
extern "C" void kernel_launch(void* const* d_in, const int* in_sizes, int n_in,
                              void* d_out, int out_size) {
    (void)in_sizes; (void)n_in; (void)out_size;

    const float* x   = (const float*)d_in[0];
    const float* Wg  = (const float*)d_in[1];
    const float* W1  = (const float*)d_in[2];
    const float* b1  = (const float*)d_in[3];
    const float* g1  = (const float*)d_in[4];
    const float* be1 = (const float*)d_in[5];
    const float* m1  = (const float*)d_in[6];
    const float* v1  = (const float*)d_in[7];
    const float* W2  = (const float*)d_in[8];
    const float* b2  = (const float*)d_in[9];
    const float* g2  = (const float*)d_in[10];
    const float* be2 = (const float*)d_in[11];
    const float* m2  = (const float*)d_in[12];
    const float* v2  = (const float*)d_in[13];
    const float* W3  = (const float*)d_in[14];
    const float* b3  = (const float*)d_in[15];
    const float* sW1 = (const float*)d_in[16];
    const float* sb1 = (const float*)d_in[17];
    const float* sg1 = (const float*)d_in[18];
    const float* sbe1= (const float*)d_in[19];
    const float* sm1 = (const float*)d_in[20];
    const float* sv1 = (const float*)d_in[21];
    const float* sW2 = (const float*)d_in[22];
    const float* sb2 = (const float*)d_in[23];
    const float* sg2 = (const float*)d_in[24];
    const float* sbe2= (const float*)d_in[25];
    const float* sm2 = (const float*)d_in[26];
    const float* sv2 = (const float*)d_in[27];
    const float* sW3 = (const float*)d_in[28];
    const float* sb3 = (const float*)d_in[29];
    float* out = (float*)d_out;

    __half *x16, *w1h, *w2h, *w3h, *bufA, *bufB;
    float *p1b, *p1s, *p1h, *p2b, *p2s, *p2h, *p3b;
    cudaGetSymbolAddress((void**)&x16,  g_x16);
    cudaGetSymbolAddress((void**)&w1h,  g_w1);
    cudaGetSymbolAddress((void**)&w2h,  g_w2);
    cudaGetSymbolAddress((void**)&w3h,  g_w3);
    cudaGetSymbolAddress((void**)&bufA, g_bufA);
    cudaGetSymbolAddress((void**)&bufB, g_bufB);
    cudaGetSymbolAddress((void**)&p1b,  g_p1b);
    cudaGetSymbolAddress((void**)&p1s,  g_p1s);
    cudaGetSymbolAddress((void**)&p1h,  g_p1h);
    cudaGetSymbolAddress((void**)&p2b,  g_p2b);
    cudaGetSymbolAddress((void**)&p2s,  g_p2s);
    cudaGetSymbolAddress((void**)&p2h,  g_p2h);
    cudaGetSymbolAddress((void**)&p3b,  g_p3b);

    // L3 fp32 scratch aliases bufA (dead after L2): ROWS_TOT*OUTD*4 == ROWS_TOT*HID*2
    float* scratch = (float*)bufA;

    cudaFuncSetAttribute(gemm_h<0, true>,  cudaFuncAttributeMaxDynamicSharedMemorySize, SMEM_BYTES);
    cudaFuncSetAttribute(gemm_h<0, false>, cudaFuncAttributeMaxDynamicSharedMemorySize, SMEM_BYTES);
    cudaFuncSetAttribute(gemm_h<1, false>, cudaFuncAttributeMaxDynamicSharedMemorySize, SMEM_BYTES);

    k_init<<<(ROWS_TOT + 255) / 256, 256>>>();
    k_gate<<<N_TOK / 8, 256>>>(x, Wg);
    k_offsets<<<1, 32>>>();
    k_scatter<<<(N_TOK + 255) / 256, 256>>>();
    k_params<<<(NE9 * HID + 255) / 256, 256>>>(
        b1, g1, be1, m1, v1, b2, g2, be2, m2, v2, b3,
        sb1, sg1, sbe1, sm1, sv1, sb2, sg2, sbe2, sm2, sv2, sb3);

    {
        struct { const float* s; __half* d; size_t n; } cv[7] = {
            { x,   x16, (size_t)N_TOK * DIM },
            { W1,  w1h, (size_t)NEXP * HID * DIM },
            { sW1, w1h + (size_t)NEXP * HID * DIM, (size_t)HID * DIM },
            { W2,  w2h, (size_t)NEXP * HID * HID },
            { sW2, w2h + (size_t)NEXP * HID * HID, (size_t)HID * HID },
            { W3,  w3h, (size_t)NEXP * OUTD * HID },
            { sW3, w3h + (size_t)NEXP * OUTD * HID, (size_t)OUTD * HID },
        };
        for (int i = 0; i < 7; i++)
            k_cvt<<<(int)((cv[i].n / 4 + 255) / 256), 256>>>(cv[i].s, cv[i].d, (int)cv[i].n);
    }

    // unified 9-expert chain:
    //   L1: gather(x16) -> bufA (half)
    //   L2: bufA -> bufB (half)            [bufA dead afterwards]
    //   L3: bufB -> scratch (fp32, aliases bufA storage)
    //   combine: scratch -> out
    dim3 grid1(HID / BN,  ROWS_TOT / BM);
    dim3 grid3(OUTD / BN, ROWS_TOT / BM);
    gemm_h<0, true><<<grid1, 256, SMEM_BYTES>>>(
        x16, w1h, p1b, p1s, p1h, bufA, DIM, HID, (long)HID * DIM);
    gemm_h<0, false><<<grid1, 256, SMEM_BYTES>>>(
        bufA, w2h, p2b, p2s, p2h, bufB, HID, HID, (long)HID * HID);
    gemm_h<1, false><<<grid3, 256, SMEM_BYTES>>>(
        bufB, w3h, p3b, nullptr, nullptr, scratch, HID, OUTD, (long)OUTD * HID);
    k_combine<<<(N_TOK * (OUTD / 4) + 255) / 256, 256>>>(scratch, out);
}